// round 11
// baseline (speedup 1.0000x reference)
#include <cuda_runtime.h>

#define NN 100000
#define EE 1600000
#define FF 128
#define GG 512
#define CC 40
#define BN_EPS 1e-5f

// ------------------- scratch (device globals; no allocation) -------------------
__device__ float g_deg[NN];
__device__ float g_dinv[NN];
__device__ float g_norm[EE];
__device__ int   g_src[EE];
__device__ int   g_dst[EE];
__device__ __align__(16) float g_xw[(size_t)NN * FF];
__device__ __align__(16) float g_agg[(size_t)NN * FF];
__device__ __align__(16) float g_h[(size_t)NN * FF];
__device__ float g_sums[GG * FF];
__device__ float g_cnt[GG];

// ------------------- small helpers (packed f32x2) -------------------
__device__ __forceinline__ unsigned long long pk2(float x, float y) {
    unsigned long long r;
    asm("mov.b64 %0,{%1,%2};" : "=l"(r) : "f"(x), "f"(y));
    return r;
}
__device__ __forceinline__ void fma2(unsigned long long& d, unsigned long long a, unsigned long long b) {
    asm("fma.rn.f32x2 %0,%1,%2,%0;" : "+l"(d) : "l"(a), "l"(b));
}
__device__ __forceinline__ float2 up2(unsigned long long v) {
    float2 r;
    asm("mov.b64 {%0,%1},%2;" : "=f"(r.x), "=f"(r.y) : "l"(v));
    return r;
}

// ------------------- setup kernels -------------------
__global__ void k_init() {
    int i = blockIdx.x * blockDim.x + threadIdx.x;
    if (i < NN) g_deg[i] = 0.f;
    if (i < GG * FF) g_sums[i] = 0.f;
    if (i < GG) g_cnt[i] = 0.f;
}

__global__ void k_deg(const int* __restrict__ ei) {
    int e = blockIdx.x * blockDim.x + threadIdx.x;
    if (e < EE) atomicAdd(&g_deg[ei[EE + e]], 1.f);
}

__global__ void k_dinv() {
    int i = blockIdx.x * blockDim.x + threadIdx.x;
    if (i < NN) g_dinv[i] = rsqrtf(g_deg[i] + 1.f);
}

__global__ void k_prep(const int* __restrict__ ei) {
    int e = blockIdx.x * blockDim.x + threadIdx.x;
    if (e < EE) {
        int s = ei[e];
        int d = ei[EE + e];
        g_src[e] = s;
        g_dst[e] = d;
        g_norm[e] = g_dinv[s] * g_dinv[d];
    }
}

// ------------------- GEMM: xw = A @ W ; agg = xw * dinv^2 (fused epilogue) ----
__global__ void __launch_bounds__(256) k_gemm(const float* __restrict__ A,
                                              const float* __restrict__ W,
                                              float* __restrict__ XWout,
                                              float* __restrict__ AGGout) {
    __shared__ float AshT[32][68];     // [k_local][row], padded
    __shared__ float Wsh[32 * 128];    // [k_local][col]
    int tid = threadIdx.x;
    int tx = tid & 31;
    int ty = tid >> 5;
    int r0 = blockIdx.x * 64;

    unsigned long long acc[4][4];      // [col][rowpair]
#pragma unroll
    for (int c = 0; c < 4; c++)
#pragma unroll
        for (int p = 0; p < 4; p++) acc[c][p] = 0ull;

    for (int kk = 0; kk < 128; kk += 32) {
#pragma unroll
        for (int t = 0; t < 2; t++) {
            int idx = tid + t * 256;       // 0..511
            int r = idx >> 3;              // 0..63
            int kq = idx & 7;              // float4 index within k-chunk
            float4 v = make_float4(0.f, 0.f, 0.f, 0.f);
            if (r0 + r < NN) v = *(const float4*)(A + (size_t)(r0 + r) * FF + kk + kq * 4);
            AshT[kq * 4 + 0][r] = v.x;
            AshT[kq * 4 + 1][r] = v.y;
            AshT[kq * 4 + 2][r] = v.z;
            AshT[kq * 4 + 3][r] = v.w;
        }
#pragma unroll
        for (int t = 0; t < 4; t++) {
            int idx = tid + t * 256;       // 0..1023
            int kl = idx >> 5;             // 0..31
            int c4 = idx & 31;
            *(float4*)(Wsh + kl * 128 + c4 * 4) =
                *(const float4*)(W + (size_t)(kk + kl) * FF + c4 * 4);
        }
        __syncthreads();
#pragma unroll
        for (int k = 0; k < 32; k++) {
            float4 a0 = *(const float4*)(&AshT[k][ty * 8]);
            float4 a1 = *(const float4*)(&AshT[k][ty * 8 + 4]);
            unsigned long long ap[4] = { pk2(a0.x, a0.y), pk2(a0.z, a0.w),
                                         pk2(a1.x, a1.y), pk2(a1.z, a1.w) };
            float4 wv = *(const float4*)(Wsh + k * 128 + tx * 4);
            unsigned long long wd[4] = { pk2(wv.x, wv.x), pk2(wv.y, wv.y),
                                         pk2(wv.z, wv.z), pk2(wv.w, wv.w) };
#pragma unroll
            for (int c = 0; c < 4; c++)
#pragma unroll
                for (int p = 0; p < 4; p++) fma2(acc[c][p], ap[p], wd[c]);
        }
        __syncthreads();
    }

#pragma unroll
    for (int p = 0; p < 4; p++) {
        float2 c0 = up2(acc[0][p]), c1 = up2(acc[1][p]);
        float2 c2 = up2(acc[2][p]), c3 = up2(acc[3][p]);
        int r = r0 + ty * 8 + p * 2;
        if (r < NN) {
            float4 v = make_float4(c0.x, c1.x, c2.x, c3.x);
            *(float4*)(XWout + (size_t)r * FF + tx * 4) = v;
            float di = g_dinv[r]; float s = di * di;
            *(float4*)(AGGout + (size_t)r * FF + tx * 4) =
                make_float4(v.x * s, v.y * s, v.z * s, v.w * s);
        }
        if (r + 1 < NN) {
            float4 v = make_float4(c0.y, c1.y, c2.y, c3.y);
            *(float4*)(XWout + (size_t)(r + 1) * FF + tx * 4) = v;
            float di = g_dinv[r + 1]; float s = di * di;
            *(float4*)(AGGout + (size_t)(r + 1) * FF + tx * 4) =
                make_float4(v.x * s, v.y * s, v.z * s, v.w * s);
        }
    }
}

// ------------------- edge scatter: agg[dst] += xw[src] * norm -------------------
// One warp per edge; each lane moves a float4 via read-only gather, then 4
// scalar no-return atomicAdds (ptxas -> RED.E.ADD.F32).
__global__ void __launch_bounds__(512) k_scatter() {
    int w = (blockIdx.x * 512 + threadIdx.x) >> 5;
    int lane = threadIdx.x & 31;
    if (w >= EE) return;
    int s = g_src[w];
    int d = g_dst[w];
    float nv = g_norm[w];
    float4 v = __ldg((const float4*)(g_xw + (size_t)s * FF + lane * 4));
    float* dp = g_agg + (size_t)d * FF + lane * 4;
    atomicAdd(dp + 0, v.x * nv);
    atomicAdd(dp + 1, v.y * nv);
    atomicAdd(dp + 2, v.z * nv);
    atomicAdd(dp + 3, v.w * nv);
}

// ------------------- h = relu(BN(agg + b)) -------------------
__global__ void k_bnrelu(const float* __restrict__ cb, const float* __restrict__ gm,
                         const float* __restrict__ bt, const float* __restrict__ mn,
                         const float* __restrict__ vr) {
    int i = blockIdx.x * blockDim.x + threadIdx.x;   // over N*F/4
    if (i >= NN * FF / 4) return;
    int f4 = (i & 31) * 4;
    float4 a  = *(const float4*)(g_agg + (size_t)i * 4);
    float4 b  = *(const float4*)(cb + f4);
    float4 g  = *(const float4*)(gm + f4);
    float4 be = *(const float4*)(bt + f4);
    float4 m  = *(const float4*)(mn + f4);
    float4 v  = *(const float4*)(vr + f4);
    float4 o;
    o.x = fmaxf((a.x + b.x - m.x) * (g.x * rsqrtf(v.x + BN_EPS)) + be.x, 0.f);
    o.y = fmaxf((a.y + b.y - m.y) * (g.y * rsqrtf(v.y + BN_EPS)) + be.y, 0.f);
    o.z = fmaxf((a.z + b.z - m.z) * (g.z * rsqrtf(v.z + BN_EPS)) + be.z, 0.f);
    o.w = fmaxf((a.w + b.w - m.w) * (g.w * rsqrtf(v.w + BN_EPS)) + be.w, 0.f);
    *(float4*)(g_h + (size_t)i * 4) = o;
}

// ------------------- pooled sums over sorted batch + final bias -------------------
#define PCH 64
__global__ void __launch_bounds__(128) k_pool(const float* __restrict__ cb,
                                              const int* __restrict__ batch) {
    int f = threadIdx.x;   // 128 features
    int n0 = blockIdx.x * PCH;
    if (n0 >= NN) return;
    int n1 = n0 + PCH; if (n1 > NN) n1 = NN;
    int cur = batch[n0];
    float acc = 0.f, cnt = 0.f;
    float bf = cb[f];
    for (int n = n0; n < n1; ++n) {
        int gid = batch[n];
        if (gid != cur) {
            atomicAdd(&g_sums[cur * FF + f], acc);
            if (f == 0) atomicAdd(&g_cnt[cur], cnt);
            acc = 0.f; cnt = 0.f; cur = gid;
        }
        acc += g_agg[(size_t)n * FF + f] + bf;
        cnt += 1.f;
    }
    atomicAdd(&g_sums[cur * FF + f], acc);
    if (f == 0) atomicAdd(&g_cnt[cur], cnt);
}

// ------------------- out = (sums/cnt) @ lin_w + lin_b -------------------
__global__ void __launch_bounds__(128) k_out(const float* __restrict__ lin_w,
                                             const float* __restrict__ lin_b,
                                             float* __restrict__ out) {
    __shared__ float p[FF];
    int g = blockIdx.x;
    int t = threadIdx.x;
    float c = g_cnt[g];
    float inv = 1.f / fmaxf(c, 1.f);
    p[t] = g_sums[g * FF + t] * inv;
    __syncthreads();
    if (t < CC) {
        float acc = lin_b[t];
#pragma unroll
        for (int k = 0; k < FF; k++) acc += p[k] * lin_w[k * CC + t];
        out[g * CC + t] = acc;
    }
}

// ------------------- launch -------------------
extern "C" void kernel_launch(void* const* d_in, const int* in_sizes, int n_in,
                              void* d_out, int out_size) {
    const float* x      = (const float*)d_in[0];
    const int*   ei     = (const int*)d_in[1];      // int32 (JAX x64 disabled)
    const int*   batch  = (const int*)d_in[2];      // int32
    const float* conv_w = (const float*)d_in[3];
    const float* conv_b = (const float*)d_in[4];
    const float* bn_g   = (const float*)d_in[5];
    const float* bn_b   = (const float*)d_in[6];
    const float* bn_m   = (const float*)d_in[7];
    const float* bn_v   = (const float*)d_in[8];
    const float* lin_w  = (const float*)d_in[9];
    const float* lin_b  = (const float*)d_in[10];
    float*       out    = (float*)d_out;

    float* h_ptr;  cudaGetSymbolAddress((void**)&h_ptr, g_h);
    float* xw_ptr; cudaGetSymbolAddress((void**)&xw_ptr, g_xw);
    float* ag_ptr; cudaGetSymbolAddress((void**)&ag_ptr, g_agg);

    const int TB = 256;
    k_init<<<(NN + TB - 1) / TB, TB>>>();
    k_deg<<<(EE + TB - 1) / TB, TB>>>(ei);
    k_dinv<<<(NN + TB - 1) / TB, TB>>>();
    k_prep<<<(EE + TB - 1) / TB, TB>>>(ei);

    const int GEMM_BLOCKS = (NN + 63) / 64;
    const int EW_BLOCKS = (NN * FF / 4 + TB - 1) / TB;
    const int SC_BLOCKS = (EE * 32 + 511) / 512;

    for (int l = 0; l < 3; ++l) {
        const float* hin = (l == 0) ? x : h_ptr;
        k_gemm<<<GEMM_BLOCKS, 256>>>(hin, conv_w + (size_t)l * FF * FF, xw_ptr, ag_ptr);
        k_scatter<<<SC_BLOCKS, 512>>>();
        if (l < 2) {
            k_bnrelu<<<EW_BLOCKS, TB>>>(conv_b + l * FF, bn_g + l * FF, bn_b + l * FF,
                                        bn_m + l * FF, bn_v + l * FF);
        } else {
            k_pool<<<(NN + PCH - 1) / PCH, 128>>>(conv_b + l * FF, batch);
        }
    }
    k_out<<<GG, 128>>>(lin_w, lin_b, out);
}

// round 12
// speedup vs baseline: 2.9494x; 2.9494x over previous
#include <cuda_runtime.h>

#define NN 100000
#define EE 1600000
#define FF 128
#define GG 512
#define CC 40
#define BN_EPS 1e-5f

// ------------------- scratch (device globals; no allocation) -------------------
__device__ int   g_count[NN];        // in-degree histogram (by dst)
__device__ float g_dinv[NN];
__device__ int   g_rowptr[NN + 1];   // CSR row pointers (by dst)
__device__ int   g_cursor[NN];
__device__ __align__(8) int2 g_edge[EE];   // {src, norm_bits} sorted by dst
__device__ __align__(16) float g_xw[(size_t)NN * FF];
__device__ __align__(16) float g_agg[(size_t)NN * FF];
__device__ __align__(16) float g_h[(size_t)NN * FF];
__device__ float g_sums[GG * FF];
__device__ float g_cnt[GG];

// ------------------- small helpers (packed f32x2) -------------------
__device__ __forceinline__ unsigned long long pk2(float x, float y) {
    unsigned long long r;
    asm("mov.b64 %0,{%1,%2};" : "=l"(r) : "f"(x), "f"(y));
    return r;
}
__device__ __forceinline__ void fma2(unsigned long long& d, unsigned long long a, unsigned long long b) {
    asm("fma.rn.f32x2 %0,%1,%2,%0;" : "+l"(d) : "l"(a), "l"(b));
}
__device__ __forceinline__ float2 up2(unsigned long long v) {
    float2 r;
    asm("mov.b64 {%0,%1},%2;" : "=f"(r.x), "=f"(r.y) : "l"(v));
    return r;
}

// ------------------- setup kernels -------------------
__global__ void k_init() {
    int i = blockIdx.x * blockDim.x + threadIdx.x;
    if (i < NN) g_count[i] = 0;
    if (i < GG * FF) g_sums[i] = 0.f;
    if (i < GG) g_cnt[i] = 0.f;
}

__global__ void k_histo(const int* __restrict__ ei) {
    int e = blockIdx.x * blockDim.x + threadIdx.x;
    if (e < EE) atomicAdd(&g_count[ei[EE + e]], 1);
}

__global__ void k_dinv() {
    int i = blockIdx.x * blockDim.x + threadIdx.x;
    if (i < NN) g_dinv[i] = rsqrtf((float)g_count[i] + 1.f);
}

// single-block exclusive scan of g_count -> g_rowptr / g_cursor (warp-shuffle based)
__global__ void __launch_bounds__(1024) k_scan() {
    __shared__ int swarp[32];
    __shared__ int s_off;
    int tid = threadIdx.x;
    int lane = tid & 31;
    int wid = tid >> 5;
    if (tid == 0) s_off = 0;
    __syncthreads();
    for (int base = 0; base < NN; base += 1024) {
        int i = base + tid;
        int v = (i < NN) ? g_count[i] : 0;
        // inclusive warp scan
        int x = v;
#pragma unroll
        for (int o = 1; o < 32; o <<= 1) {
            int t = __shfl_up_sync(0xffffffffu, x, o);
            if (lane >= o) x += t;
        }
        if (lane == 31) swarp[wid] = x;
        __syncthreads();
        if (wid == 0) {
            int y = swarp[lane];
            int z = y;
#pragma unroll
            for (int o = 1; o < 32; o <<= 1) {
                int t = __shfl_up_sync(0xffffffffu, z, o);
                if (lane >= o) z += t;
            }
            swarp[lane] = z - y;   // exclusive warp offsets
        }
        __syncthreads();
        int incl = x + swarp[wid];
        int excl = incl - v;
        int off = s_off;
        if (i < NN) { g_rowptr[i] = off + excl; g_cursor[i] = off + excl; }
        // chunk total = inclusive value of last thread
        __syncthreads();
        if (tid == 1023) s_off = off + incl;
        __syncthreads();
    }
    if (tid == 0) g_rowptr[NN] = s_off;
}

__global__ void k_fill(const int* __restrict__ ei) {
    int e = blockIdx.x * blockDim.x + threadIdx.x;
    if (e < EE) {
        int s = ei[e];
        int d = ei[EE + e];
        float nv = g_dinv[s] * g_dinv[d];
        int pos = atomicAdd(&g_cursor[d], 1);
        g_edge[pos] = make_int2(s, __float_as_int(nv));
    }
}

// ------------------- GEMM: xw = A @ W -------------------
__global__ void __launch_bounds__(256) k_gemm(const float* __restrict__ A,
                                              const float* __restrict__ W,
                                              float* __restrict__ XWout) {
    __shared__ float AshT[32][68];     // [k_local][row], padded
    __shared__ float Wsh[32 * 128];    // [k_local][col]
    int tid = threadIdx.x;
    int tx = tid & 31;
    int ty = tid >> 5;
    int r0 = blockIdx.x * 64;

    unsigned long long acc[4][4];      // [col][rowpair]
#pragma unroll
    for (int c = 0; c < 4; c++)
#pragma unroll
        for (int p = 0; p < 4; p++) acc[c][p] = 0ull;

    for (int kk = 0; kk < 128; kk += 32) {
#pragma unroll
        for (int t = 0; t < 2; t++) {
            int idx = tid + t * 256;       // 0..511
            int r = idx >> 3;              // 0..63
            int kq = idx & 7;
            float4 v = make_float4(0.f, 0.f, 0.f, 0.f);
            if (r0 + r < NN) v = *(const float4*)(A + (size_t)(r0 + r) * FF + kk + kq * 4);
            AshT[kq * 4 + 0][r] = v.x;
            AshT[kq * 4 + 1][r] = v.y;
            AshT[kq * 4 + 2][r] = v.z;
            AshT[kq * 4 + 3][r] = v.w;
        }
#pragma unroll
        for (int t = 0; t < 4; t++) {
            int idx = tid + t * 256;       // 0..1023
            int kl = idx >> 5;
            int c4 = idx & 31;
            *(float4*)(Wsh + kl * 128 + c4 * 4) =
                *(const float4*)(W + (size_t)(kk + kl) * FF + c4 * 4);
        }
        __syncthreads();
#pragma unroll
        for (int k = 0; k < 32; k++) {
            float4 a0 = *(const float4*)(&AshT[k][ty * 8]);
            float4 a1 = *(const float4*)(&AshT[k][ty * 8 + 4]);
            unsigned long long ap[4] = { pk2(a0.x, a0.y), pk2(a0.z, a0.w),
                                         pk2(a1.x, a1.y), pk2(a1.z, a1.w) };
            float4 wv = *(const float4*)(Wsh + k * 128 + tx * 4);
            unsigned long long wd[4] = { pk2(wv.x, wv.x), pk2(wv.y, wv.y),
                                         pk2(wv.z, wv.z), pk2(wv.w, wv.w) };
#pragma unroll
            for (int c = 0; c < 4; c++)
#pragma unroll
                for (int p = 0; p < 4; p++) fma2(acc[c][p], ap[p], wd[c]);
        }
        __syncthreads();
    }

#pragma unroll
    for (int p = 0; p < 4; p++) {
        float2 c0 = up2(acc[0][p]), c1 = up2(acc[1][p]);
        float2 c2 = up2(acc[2][p]), c3 = up2(acc[3][p]);
        int r = r0 + ty * 8 + p * 2;
        if (r < NN)
            *(float4*)(XWout + (size_t)r * FF + tx * 4) = make_float4(c0.x, c1.x, c2.x, c3.x);
        if (r + 1 < NN)
            *(float4*)(XWout + (size_t)(r + 1) * FF + tx * 4) = make_float4(c0.y, c1.y, c2.y, c3.y);
    }
}

// ------------------- gather aggregation: warp per node ------------------------
// acc = xw[n]*dinv[n]^2 + sum_{e in CSR[n]} xw[src_e]*norm_e
// MODE bn: h = relu((acc + b - mean)*scale + beta)   MODE raw: agg = acc
__device__ __forceinline__ float4 agg_node(int w, int lane) {
    int f4 = lane * 4;
    float di = g_dinv[w];
    float sl = di * di;
    const float4 xs = *(const float4*)(g_xw + (size_t)w * FF + f4);
    float4 acc = make_float4(xs.x * sl, xs.y * sl, xs.z * sl, xs.w * sl);
    int beg = g_rowptr[w];
    int end = g_rowptr[w + 1];
    for (int e = beg; e < end; e++) {
        int2 ed = __ldg(&g_edge[e]);
        float nv = __int_as_float(ed.y);
        float4 v = __ldg((const float4*)(g_xw + (size_t)ed.x * FF + f4));
        acc.x = fmaf(v.x, nv, acc.x);
        acc.y = fmaf(v.y, nv, acc.y);
        acc.z = fmaf(v.z, nv, acc.z);
        acc.w = fmaf(v.w, nv, acc.w);
    }
    return acc;
}

__global__ void __launch_bounds__(256) k_agg_bn(const float* __restrict__ cb,
                                                const float* __restrict__ gm,
                                                const float* __restrict__ bt,
                                                const float* __restrict__ mn,
                                                const float* __restrict__ vr) {
    int w = (blockIdx.x * 256 + threadIdx.x) >> 5;
    int lane = threadIdx.x & 31;
    if (w >= NN) return;
    float4 acc = agg_node(w, lane);
    int f4 = lane * 4;
    float4 b  = *(const float4*)(cb + f4);
    float4 g  = *(const float4*)(gm + f4);
    float4 be = *(const float4*)(bt + f4);
    float4 m  = *(const float4*)(mn + f4);
    float4 v  = *(const float4*)(vr + f4);
    float4 o;
    o.x = fmaxf((acc.x + b.x - m.x) * (g.x * rsqrtf(v.x + BN_EPS)) + be.x, 0.f);
    o.y = fmaxf((acc.y + b.y - m.y) * (g.y * rsqrtf(v.y + BN_EPS)) + be.y, 0.f);
    o.z = fmaxf((acc.z + b.z - m.z) * (g.z * rsqrtf(v.z + BN_EPS)) + be.z, 0.f);
    o.w = fmaxf((acc.w + b.w - m.w) * (g.w * rsqrtf(v.w + BN_EPS)) + be.w, 0.f);
    *(float4*)(g_h + (size_t)w * FF + f4) = o;
}

__global__ void __launch_bounds__(256) k_agg_raw() {
    int w = (blockIdx.x * 256 + threadIdx.x) >> 5;
    int lane = threadIdx.x & 31;
    if (w >= NN) return;
    float4 acc = agg_node(w, lane);
    *(float4*)(g_agg + (size_t)w * FF + lane * 4) = acc;
}

// ------------------- pooled sums over sorted batch + final bias ---------------
#define PCH 64
__global__ void __launch_bounds__(128) k_pool(const float* __restrict__ cb,
                                              const int* __restrict__ batch) {
    int f = threadIdx.x;   // 128 features
    int n0 = blockIdx.x * PCH;
    if (n0 >= NN) return;
    int n1 = n0 + PCH; if (n1 > NN) n1 = NN;
    int cur = batch[n0];
    float acc = 0.f, cnt = 0.f;
    float bf = cb[f];
    for (int n = n0; n < n1; ++n) {
        int gid = batch[n];
        if (gid != cur) {
            atomicAdd(&g_sums[cur * FF + f], acc);
            if (f == 0) atomicAdd(&g_cnt[cur], cnt);
            acc = 0.f; cnt = 0.f; cur = gid;
        }
        acc += g_agg[(size_t)n * FF + f] + bf;
        cnt += 1.f;
    }
    atomicAdd(&g_sums[cur * FF + f], acc);
    if (f == 0) atomicAdd(&g_cnt[cur], cnt);
}

// ------------------- out = (sums/cnt) @ lin_w + lin_b -------------------
__global__ void __launch_bounds__(128) k_out(const float* __restrict__ lin_w,
                                             const float* __restrict__ lin_b,
                                             float* __restrict__ out) {
    __shared__ float p[FF];
    int g = blockIdx.x;
    int t = threadIdx.x;
    float c = g_cnt[g];
    float inv = 1.f / fmaxf(c, 1.f);
    p[t] = g_sums[g * FF + t] * inv;
    __syncthreads();
    if (t < CC) {
        float acc = lin_b[t];
#pragma unroll
        for (int k = 0; k < FF; k++) acc += p[k] * lin_w[k * CC + t];
        out[g * CC + t] = acc;
    }
}

// ------------------- launch -------------------
extern "C" void kernel_launch(void* const* d_in, const int* in_sizes, int n_in,
                              void* d_out, int out_size) {
    const float* x      = (const float*)d_in[0];
    const int*   ei     = (const int*)d_in[1];      // int32 (JAX x64 disabled)
    const int*   batch  = (const int*)d_in[2];      // int32
    const float* conv_w = (const float*)d_in[3];
    const float* conv_b = (const float*)d_in[4];
    const float* bn_g   = (const float*)d_in[5];
    const float* bn_b   = (const float*)d_in[6];
    const float* bn_m   = (const float*)d_in[7];
    const float* bn_v   = (const float*)d_in[8];
    const float* lin_w  = (const float*)d_in[9];
    const float* lin_b  = (const float*)d_in[10];
    float*       out    = (float*)d_out;

    float* h_ptr;  cudaGetSymbolAddress((void**)&h_ptr, g_h);
    float* xw_ptr; cudaGetSymbolAddress((void**)&xw_ptr, g_xw);

    const int TB = 256;
    // CSR build (once; reused by all 3 layers)
    k_init<<<(NN + TB - 1) / TB, TB>>>();
    k_histo<<<(EE + TB - 1) / TB, TB>>>(ei);
    k_dinv<<<(NN + TB - 1) / TB, TB>>>();
    k_scan<<<1, 1024>>>();
    k_fill<<<(EE + TB - 1) / TB, TB>>>(ei);

    const int GEMM_BLOCKS = (NN + 63) / 64;
    const int AGG_BLOCKS = (NN * 32 + TB - 1) / TB;

    for (int l = 0; l < 3; ++l) {
        const float* hin = (l == 0) ? x : h_ptr;
        k_gemm<<<GEMM_BLOCKS, 256>>>(hin, conv_w + (size_t)l * FF * FF, xw_ptr);
        if (l < 2) {
            k_agg_bn<<<AGG_BLOCKS, TB>>>(conv_b + l * FF, bn_g + l * FF, bn_b + l * FF,
                                         bn_m + l * FF, bn_v + l * FF);
        } else {
            k_agg_raw<<<AGG_BLOCKS, TB>>>();
            k_pool<<<(NN + PCH - 1) / PCH, 128>>>(conv_b + l * FF, batch);
        }
    }
    k_out<<<GG, 128>>>(lin_w, lin_b, out);
}

// round 14
// speedup vs baseline: 3.3159x; 1.1243x over previous
#include <cuda_runtime.h>

#define NN 100000
#define EE 1600000
#define FF 128
#define GG 512
#define CC 40
#define BN_EPS 1e-5f

// ------------------- scratch (device globals; no allocation) -------------------
__device__ int   g_count[NN];        // in-degree histogram (by dst)
__device__ float g_dinv[NN];
__device__ int   g_rowbeg[NN];       // segment start per dst (unordered CSR)
__device__ int   g_cursor[NN];
__device__ int   g_total;
__device__ __align__(8) int2 g_edge[EE];   // {src, norm_bits} grouped by dst
__device__ __align__(16) float g_xw[(size_t)NN * FF];
__device__ __align__(16) float g_agg[(size_t)NN * FF];
__device__ __align__(16) float g_h[(size_t)NN * FF];
__device__ float g_sums[GG * FF];
__device__ float g_cnt[GG];

// ------------------- small helpers (packed f32x2) -------------------
__device__ __forceinline__ unsigned long long pk2(float x, float y) {
    unsigned long long r;
    asm("mov.b64 %0,{%1,%2};" : "=l"(r) : "f"(x), "f"(y));
    return r;
}
__device__ __forceinline__ void fma2(unsigned long long& d, unsigned long long a, unsigned long long b) {
    asm("fma.rn.f32x2 %0,%1,%2,%0;" : "+l"(d) : "l"(a), "l"(b));
}
__device__ __forceinline__ float2 up2(unsigned long long v) {
    float2 r;
    asm("mov.b64 {%0,%1},%2;" : "=f"(r.x), "=f"(r.y) : "l"(v));
    return r;
}

// ------------------- setup kernels -------------------
__global__ void k_init() {
    int i = blockIdx.x * blockDim.x + threadIdx.x;
    if (i < NN) g_count[i] = 0;
    if (i < GG * FF) g_sums[i] = 0.f;
    if (i < GG) g_cnt[i] = 0.f;
    if (i == 0) g_total = 0;
}

__global__ void k_histo(const int* __restrict__ ei) {
    int e = blockIdx.x * blockDim.x + threadIdx.x;
    if (e < EE) atomicAdd(&g_count[ei[EE + e]], 1);
}

// dinv + unordered segment assignment (replaces the serial prefix scan)
__global__ void k_seg() {
    int i = blockIdx.x * blockDim.x + threadIdx.x;
    if (i < NN) {
        int c = g_count[i];
        g_dinv[i] = rsqrtf((float)c + 1.f);
        int start = atomicAdd(&g_total, c);
        g_rowbeg[i] = start;
        g_cursor[i] = start;
    }
}

__global__ void k_fill(const int* __restrict__ ei) {
    int e = blockIdx.x * blockDim.x + threadIdx.x;
    if (e < EE) {
        int s = ei[e];
        int d = ei[EE + e];
        float nv = g_dinv[s] * g_dinv[d];
        int pos = atomicAdd(&g_cursor[d], 1);
        g_edge[pos] = make_int2(s, __float_as_int(nv));
    }
}

// ------------------- GEMM: xw = A @ W -------------------
__global__ void __launch_bounds__(256) k_gemm(const float* __restrict__ A,
                                              const float* __restrict__ W,
                                              float* __restrict__ XWout) {
    __shared__ float AshT[32][68];     // [k_local][row], padded
    __shared__ float Wsh[32 * 128];    // [k_local][col]
    int tid = threadIdx.x;
    int tx = tid & 31;
    int ty = tid >> 5;
    int r0 = blockIdx.x * 64;

    unsigned long long acc[4][4];      // [col][rowpair]
#pragma unroll
    for (int c = 0; c < 4; c++)
#pragma unroll
        for (int p = 0; p < 4; p++) acc[c][p] = 0ull;

    for (int kk = 0; kk < 128; kk += 32) {
#pragma unroll
        for (int t = 0; t < 2; t++) {
            int idx = tid + t * 256;       // 0..511
            int r = idx >> 3;              // 0..63
            int kq = idx & 7;
            float4 v = make_float4(0.f, 0.f, 0.f, 0.f);
            if (r0 + r < NN) v = *(const float4*)(A + (size_t)(r0 + r) * FF + kk + kq * 4);
            AshT[kq * 4 + 0][r] = v.x;
            AshT[kq * 4 + 1][r] = v.y;
            AshT[kq * 4 + 2][r] = v.z;
            AshT[kq * 4 + 3][r] = v.w;
        }
#pragma unroll
        for (int t = 0; t < 4; t++) {
            int idx = tid + t * 256;       // 0..1023
            int kl = idx >> 5;
            int c4 = idx & 31;
            *(float4*)(Wsh + kl * 128 + c4 * 4) =
                *(const float4*)(W + (size_t)(kk + kl) * FF + c4 * 4);
        }
        __syncthreads();
#pragma unroll
        for (int k = 0; k < 32; k++) {
            float4 a0 = *(const float4*)(&AshT[k][ty * 8]);
            float4 a1 = *(const float4*)(&AshT[k][ty * 8 + 4]);
            unsigned long long ap[4] = { pk2(a0.x, a0.y), pk2(a0.z, a0.w),
                                         pk2(a1.x, a1.y), pk2(a1.z, a1.w) };
            float4 wv = *(const float4*)(Wsh + k * 128 + tx * 4);
            unsigned long long wd[4] = { pk2(wv.x, wv.x), pk2(wv.y, wv.y),
                                         pk2(wv.z, wv.z), pk2(wv.w, wv.w) };
#pragma unroll
            for (int c = 0; c < 4; c++)
#pragma unroll
                for (int p = 0; p < 4; p++) fma2(acc[c][p], ap[p], wd[c]);
        }
        __syncthreads();
    }

#pragma unroll
    for (int p = 0; p < 4; p++) {
        float2 c0 = up2(acc[0][p]), c1 = up2(acc[1][p]);
        float2 c2 = up2(acc[2][p]), c3 = up2(acc[3][p]);
        int r = r0 + ty * 8 + p * 2;
        if (r < NN)
            *(float4*)(XWout + (size_t)r * FF + tx * 4) = make_float4(c0.x, c1.x, c2.x, c3.x);
        if (r + 1 < NN)
            *(float4*)(XWout + (size_t)(r + 1) * FF + tx * 4) = make_float4(c0.y, c1.y, c2.y, c3.y);
    }
}

// ------------------- gather aggregation: warp per node ------------------------
// acc = xw[n]*dinv[n]^2 + sum_{e in seg(n)} xw[src_e]*norm_e
__device__ __forceinline__ float4 agg_node(int w, int lane) {
    int f4 = lane * 4;
    float di = g_dinv[w];
    float sl = di * di;
    const float4 xs = *(const float4*)(g_xw + (size_t)w * FF + f4);
    float4 acc = make_float4(xs.x * sl, xs.y * sl, xs.z * sl, xs.w * sl);
    int beg = g_rowbeg[w];
    int end = beg + g_count[w];
    int e = beg;
    // two edges per iteration: independent loads double MLP on the chain
    for (; e + 1 < end; e += 2) {
        int2 e0 = __ldg(&g_edge[e]);
        int2 e1 = __ldg(&g_edge[e + 1]);
        float4 v0 = __ldg((const float4*)(g_xw + (size_t)e0.x * FF + f4));
        float4 v1 = __ldg((const float4*)(g_xw + (size_t)e1.x * FF + f4));
        float n0 = __int_as_float(e0.y);
        float n1 = __int_as_float(e1.y);
        acc.x = fmaf(v0.x, n0, acc.x); acc.y = fmaf(v0.y, n0, acc.y);
        acc.z = fmaf(v0.z, n0, acc.z); acc.w = fmaf(v0.w, n0, acc.w);
        acc.x = fmaf(v1.x, n1, acc.x); acc.y = fmaf(v1.y, n1, acc.y);
        acc.z = fmaf(v1.z, n1, acc.z); acc.w = fmaf(v1.w, n1, acc.w);
    }
    if (e < end) {
        int2 ed = __ldg(&g_edge[e]);
        float nv = __int_as_float(ed.y);
        float4 v = __ldg((const float4*)(g_xw + (size_t)ed.x * FF + f4));
        acc.x = fmaf(v.x, nv, acc.x); acc.y = fmaf(v.y, nv, acc.y);
        acc.z = fmaf(v.z, nv, acc.z); acc.w = fmaf(v.w, nv, acc.w);
    }
    return acc;
}

__global__ void __launch_bounds__(256) k_agg_bn(const float* __restrict__ cb,
                                                const float* __restrict__ gm,
                                                const float* __restrict__ bt,
                                                const float* __restrict__ mn,
                                                const float* __restrict__ vr) {
    int w = (blockIdx.x * 256 + threadIdx.x) >> 5;
    int lane = threadIdx.x & 31;
    if (w >= NN) return;
    float4 acc = agg_node(w, lane);
    int f4 = lane * 4;
    float4 b  = *(const float4*)(cb + f4);
    float4 g  = *(const float4*)(gm + f4);
    float4 be = *(const float4*)(bt + f4);
    float4 m  = *(const float4*)(mn + f4);
    float4 v  = *(const float4*)(vr + f4);
    float4 o;
    o.x = fmaxf((acc.x + b.x - m.x) * (g.x * rsqrtf(v.x + BN_EPS)) + be.x, 0.f);
    o.y = fmaxf((acc.y + b.y - m.y) * (g.y * rsqrtf(v.y + BN_EPS)) + be.y, 0.f);
    o.z = fmaxf((acc.z + b.z - m.z) * (g.z * rsqrtf(v.z + BN_EPS)) + be.z, 0.f);
    o.w = fmaxf((acc.w + b.w - m.w) * (g.w * rsqrtf(v.w + BN_EPS)) + be.w, 0.f);
    *(float4*)(g_h + (size_t)w * FF + f4) = o;
}

__global__ void __launch_bounds__(256) k_agg_raw() {
    int w = (blockIdx.x * 256 + threadIdx.x) >> 5;
    int lane = threadIdx.x & 31;
    if (w >= NN) return;
    float4 acc = agg_node(w, lane);
    *(float4*)(g_agg + (size_t)w * FF + lane * 4) = acc;
}

// ------------------- pooled sums over sorted batch + final bias ---------------
#define PCH 64
__global__ void __launch_bounds__(128) k_pool(const float* __restrict__ cb,
                                              const int* __restrict__ batch) {
    int f = threadIdx.x;   // 128 features
    int n0 = blockIdx.x * PCH;
    if (n0 >= NN) return;
    int n1 = n0 + PCH; if (n1 > NN) n1 = NN;
    int cur = batch[n0];
    float acc = 0.f, cnt = 0.f;
    float bf = cb[f];
    for (int n = n0; n < n1; ++n) {
        int gid = batch[n];
        if (gid != cur) {
            atomicAdd(&g_sums[cur * FF + f], acc);
            if (f == 0) atomicAdd(&g_cnt[cur], cnt);
            acc = 0.f; cnt = 0.f; cur = gid;
        }
        acc += g_agg[(size_t)n * FF + f] + bf;
        cnt += 1.f;
    }
    atomicAdd(&g_sums[cur * FF + f], acc);
    if (f == 0) atomicAdd(&g_cnt[cur], cnt);
}

// ------------------- out = (sums/cnt) @ lin_w + lin_b -------------------
__global__ void __launch_bounds__(128) k_out(const float* __restrict__ lin_w,
                                             const float* __restrict__ lin_b,
                                             float* __restrict__ out) {
    __shared__ float p[FF];
    int g = blockIdx.x;
    int t = threadIdx.x;
    float c = g_cnt[g];
    float inv = 1.f / fmaxf(c, 1.f);
    p[t] = g_sums[g * FF + t] * inv;
    __syncthreads();
    if (t < CC) {
        float acc = lin_b[t];
#pragma unroll
        for (int k = 0; k < FF; k++) acc += p[k] * lin_w[k * CC + t];
        out[g * CC + t] = acc;
    }
}

// ------------------- launch -------------------
extern "C" void kernel_launch(void* const* d_in, const int* in_sizes, int n_in,
                              void* d_out, int out_size) {
    const float* x      = (const float*)d_in[0];
    const int*   ei     = (const int*)d_in[1];      // int32 (JAX x64 disabled)
    const int*   batch  = (const int*)d_in[2];      // int32
    const float* conv_w = (const float*)d_in[3];
    const float* conv_b = (const float*)d_in[4];
    const float* bn_g   = (const float*)d_in[5];
    const float* bn_b   = (const float*)d_in[6];
    const float* bn_m   = (const float*)d_in[7];
    const float* bn_v   = (const float*)d_in[8];
    const float* lin_w  = (const float*)d_in[9];
    const float* lin_b  = (const float*)d_in[10];
    float*       out    = (float*)d_out;

    float* h_ptr;  cudaGetSymbolAddress((void**)&h_ptr, g_h);
    float* xw_ptr; cudaGetSymbolAddress((void**)&xw_ptr, g_xw);

    const int TB = 256;
    // unordered-CSR build (once; reused by all 3 layers)
    k_init<<<(NN + TB - 1) / TB, TB>>>();
    k_histo<<<(EE + TB - 1) / TB, TB>>>(ei);
    k_seg<<<(NN + TB - 1) / TB, TB>>>();
    k_fill<<<(EE + TB - 1) / TB, TB>>>(ei);

    const int GEMM_BLOCKS = (NN + 63) / 64;
    const int AGG_BLOCKS = (NN * 32 + TB - 1) / TB;

    for (int l = 0; l < 3; ++l) {
        const float* hin = (l == 0) ? x : h_ptr;
        k_gemm<<<GEMM_BLOCKS, 256>>>(hin, conv_w + (size_t)l * FF * FF, xw_ptr);
        if (l < 2) {
            k_agg_bn<<<AGG_BLOCKS, TB>>>(conv_b + l * FF, bn_g + l * FF, bn_b + l * FF,
                                         bn_m + l * FF, bn_v + l * FF);
        } else {
            k_agg_raw<<<AGG_BLOCKS, TB>>>();
            k_pool<<<(NN + PCH - 1) / PCH, 128>>>(conv_b + l * FF, batch);
        }
    }
    k_out<<<GG, 128>>>(lin_w, lin_b, out);
}

// round 15
// speedup vs baseline: 3.6895x; 1.1127x over previous
#include <cuda_runtime.h>
#include <cuda_fp16.h>

#define NN 100000
#define EE 1600000
#define FF 128
#define GG 512
#define CC 40
#define BN_EPS 1e-5f

// ------------------- scratch (device globals; no allocation) -------------------
__device__ int   g_count[NN];        // in-degree histogram (by dst)
__device__ float g_dinv[NN];
__device__ int   g_rowbeg[NN];       // segment start per dst (unordered CSR)
__device__ int   g_cursor[NN];
__device__ int   g_total;
__device__ __align__(8) int2 g_edge[EE];   // {src, norm_bits} grouped by dst
__device__ __align__(16) __half g_xwh[(size_t)NN * FF];  // fp16 xw (gather payload)
__device__ __align__(16) float g_agg[(size_t)NN * FF];
__device__ __align__(16) float g_h[(size_t)NN * FF];
__device__ float g_sums[GG * FF];
__device__ float g_cnt[GG];

// ------------------- small helpers (packed f32x2) -------------------
__device__ __forceinline__ unsigned long long pk2(float x, float y) {
    unsigned long long r;
    asm("mov.b64 %0,{%1,%2};" : "=l"(r) : "f"(x), "f"(y));
    return r;
}
__device__ __forceinline__ void fma2(unsigned long long& d, unsigned long long a, unsigned long long b) {
    asm("fma.rn.f32x2 %0,%1,%2,%0;" : "+l"(d) : "l"(a), "l"(b));
}
__device__ __forceinline__ float2 up2(unsigned long long v) {
    float2 r;
    asm("mov.b64 {%0,%1},%2;" : "=f"(r.x), "=f"(r.y) : "l"(v));
    return r;
}
__device__ __forceinline__ unsigned h2u(__half2 h) { return *(unsigned*)&h; }
__device__ __forceinline__ __half2 u2h(unsigned u) { return *(__half2*)&u; }

// ------------------- setup kernels -------------------
__global__ void k_init() {
    int i = blockIdx.x * blockDim.x + threadIdx.x;
    if (i < NN) g_count[i] = 0;
    if (i < GG * FF) g_sums[i] = 0.f;
    if (i < GG) g_cnt[i] = 0.f;
    if (i == 0) g_total = 0;
}

__global__ void k_histo(const int* __restrict__ ei) {
    int e = blockIdx.x * blockDim.x + threadIdx.x;
    if (e < EE) atomicAdd(&g_count[ei[EE + e]], 1);
}

// dinv + unordered segment assignment
__global__ void k_seg() {
    int i = blockIdx.x * blockDim.x + threadIdx.x;
    if (i < NN) {
        int c = g_count[i];
        g_dinv[i] = rsqrtf((float)c + 1.f);
        int start = atomicAdd(&g_total, c);
        g_rowbeg[i] = start;
        g_cursor[i] = start;
    }
}

__global__ void k_fill(const int* __restrict__ ei) {
    int e = blockIdx.x * blockDim.x + threadIdx.x;
    if (e < EE) {
        int s = ei[e];
        int d = ei[EE + e];
        float nv = g_dinv[s] * g_dinv[d];
        int pos = atomicAdd(&g_cursor[d], 1);
        g_edge[pos] = make_int2(s, __float_as_int(nv));
    }
}

// ------------------- GEMM: xwh = fp16(A @ W) -------------------
__global__ void __launch_bounds__(256) k_gemm(const float* __restrict__ A,
                                              const float* __restrict__ W) {
    __shared__ float AshT[32][68];     // [k_local][row], padded
    __shared__ float Wsh[32 * 128];    // [k_local][col]
    int tid = threadIdx.x;
    int tx = tid & 31;
    int ty = tid >> 5;
    int r0 = blockIdx.x * 64;

    unsigned long long acc[4][4];      // [col][rowpair]
#pragma unroll
    for (int c = 0; c < 4; c++)
#pragma unroll
        for (int p = 0; p < 4; p++) acc[c][p] = 0ull;

    for (int kk = 0; kk < 128; kk += 32) {
#pragma unroll
        for (int t = 0; t < 2; t++) {
            int idx = tid + t * 256;       // 0..511
            int r = idx >> 3;              // 0..63
            int kq = idx & 7;
            float4 v = make_float4(0.f, 0.f, 0.f, 0.f);
            if (r0 + r < NN) v = *(const float4*)(A + (size_t)(r0 + r) * FF + kk + kq * 4);
            AshT[kq * 4 + 0][r] = v.x;
            AshT[kq * 4 + 1][r] = v.y;
            AshT[kq * 4 + 2][r] = v.z;
            AshT[kq * 4 + 3][r] = v.w;
        }
#pragma unroll
        for (int t = 0; t < 4; t++) {
            int idx = tid + t * 256;       // 0..1023
            int kl = idx >> 5;
            int c4 = idx & 31;
            *(float4*)(Wsh + kl * 128 + c4 * 4) =
                *(const float4*)(W + (size_t)(kk + kl) * FF + c4 * 4);
        }
        __syncthreads();
#pragma unroll
        for (int k = 0; k < 32; k++) {
            float4 a0 = *(const float4*)(&AshT[k][ty * 8]);
            float4 a1 = *(const float4*)(&AshT[k][ty * 8 + 4]);
            unsigned long long ap[4] = { pk2(a0.x, a0.y), pk2(a0.z, a0.w),
                                         pk2(a1.x, a1.y), pk2(a1.z, a1.w) };
            float4 wv = *(const float4*)(Wsh + k * 128 + tx * 4);
            unsigned long long wd[4] = { pk2(wv.x, wv.x), pk2(wv.y, wv.y),
                                         pk2(wv.z, wv.z), pk2(wv.w, wv.w) };
#pragma unroll
            for (int c = 0; c < 4; c++)
#pragma unroll
                for (int p = 0; p < 4; p++) fma2(acc[c][p], ap[p], wd[c]);
        }
        __syncthreads();
    }

#pragma unroll
    for (int p = 0; p < 4; p++) {
        float2 c0 = up2(acc[0][p]), c1 = up2(acc[1][p]);
        float2 c2 = up2(acc[2][p]), c3 = up2(acc[3][p]);
        int r = r0 + ty * 8 + p * 2;
        if (r < NN) {
            uint2 o;
            o.x = h2u(__floats2half2_rn(c0.x, c1.x));
            o.y = h2u(__floats2half2_rn(c2.x, c3.x));
            *(uint2*)(g_xwh + (size_t)r * FF + tx * 4) = o;
        }
        if (r + 1 < NN) {
            uint2 o;
            o.x = h2u(__floats2half2_rn(c0.y, c1.y));
            o.y = h2u(__floats2half2_rn(c2.y, c3.y));
            *(uint2*)(g_xwh + (size_t)(r + 1) * FF + tx * 4) = o;
        }
    }
}

// ------------------- gather aggregation: warp per node ------------------------
// acc = xwh[n]*dinv[n]^2 + sum_{e in seg(n)} xwh[src_e]*norm_e   (fp32 accum)
__device__ __forceinline__ float4 h4_to_f4(uint2 raw) {
    float2 lo = __half22float2(u2h(raw.x));
    float2 hi = __half22float2(u2h(raw.y));
    return make_float4(lo.x, lo.y, hi.x, hi.y);
}

__device__ __forceinline__ float4 agg_node(int w, int lane) {
    int f4 = lane * 4;
    float di = g_dinv[w];
    float sl = di * di;
    float4 xs = h4_to_f4(__ldg((const uint2*)(g_xwh + (size_t)w * FF + f4)));
    float4 acc = make_float4(xs.x * sl, xs.y * sl, xs.z * sl, xs.w * sl);
    int beg = g_rowbeg[w];
    int end = beg + g_count[w];
    int e = beg;
    for (; e + 1 < end; e += 2) {
        int2 e0 = __ldg(&g_edge[e]);
        int2 e1 = __ldg(&g_edge[e + 1]);
        float4 v0 = h4_to_f4(__ldg((const uint2*)(g_xwh + (size_t)e0.x * FF + f4)));
        float4 v1 = h4_to_f4(__ldg((const uint2*)(g_xwh + (size_t)e1.x * FF + f4)));
        float n0 = __int_as_float(e0.y);
        float n1 = __int_as_float(e1.y);
        acc.x = fmaf(v0.x, n0, acc.x); acc.y = fmaf(v0.y, n0, acc.y);
        acc.z = fmaf(v0.z, n0, acc.z); acc.w = fmaf(v0.w, n0, acc.w);
        acc.x = fmaf(v1.x, n1, acc.x); acc.y = fmaf(v1.y, n1, acc.y);
        acc.z = fmaf(v1.z, n1, acc.z); acc.w = fmaf(v1.w, n1, acc.w);
    }
    if (e < end) {
        int2 ed = __ldg(&g_edge[e]);
        float nv = __int_as_float(ed.y);
        float4 v = h4_to_f4(__ldg((const uint2*)(g_xwh + (size_t)ed.x * FF + f4)));
        acc.x = fmaf(v.x, nv, acc.x); acc.y = fmaf(v.y, nv, acc.y);
        acc.z = fmaf(v.z, nv, acc.z); acc.w = fmaf(v.w, nv, acc.w);
    }
    return acc;
}

__global__ void __launch_bounds__(256) k_agg_bn(const float* __restrict__ cb,
                                                const float* __restrict__ gm,
                                                const float* __restrict__ bt,
                                                const float* __restrict__ mn,
                                                const float* __restrict__ vr) {
    int w = (blockIdx.x * 256 + threadIdx.x) >> 5;
    int lane = threadIdx.x & 31;
    if (w >= NN) return;
    float4 acc = agg_node(w, lane);
    int f4 = lane * 4;
    float4 b  = *(const float4*)(cb + f4);
    float4 g  = *(const float4*)(gm + f4);
    float4 be = *(const float4*)(bt + f4);
    float4 m  = *(const float4*)(mn + f4);
    float4 v  = *(const float4*)(vr + f4);
    float4 o;
    o.x = fmaxf((acc.x + b.x - m.x) * (g.x * rsqrtf(v.x + BN_EPS)) + be.x, 0.f);
    o.y = fmaxf((acc.y + b.y - m.y) * (g.y * rsqrtf(v.y + BN_EPS)) + be.y, 0.f);
    o.z = fmaxf((acc.z + b.z - m.z) * (g.z * rsqrtf(v.z + BN_EPS)) + be.z, 0.f);
    o.w = fmaxf((acc.w + b.w - m.w) * (g.w * rsqrtf(v.w + BN_EPS)) + be.w, 0.f);
    *(float4*)(g_h + (size_t)w * FF + f4) = o;
}

__global__ void __launch_bounds__(256) k_agg_raw() {
    int w = (blockIdx.x * 256 + threadIdx.x) >> 5;
    int lane = threadIdx.x & 31;
    if (w >= NN) return;
    float4 acc = agg_node(w, lane);
    *(float4*)(g_agg + (size_t)w * FF + lane * 4) = acc;
}

// ------------------- pooled sums over sorted batch + final bias ---------------
#define PCH 64
__global__ void __launch_bounds__(128) k_pool(const float* __restrict__ cb,
                                              const int* __restrict__ batch) {
    int f = threadIdx.x;   // 128 features
    int n0 = blockIdx.x * PCH;
    if (n0 >= NN) return;
    int n1 = n0 + PCH; if (n1 > NN) n1 = NN;
    int cur = batch[n0];
    float acc = 0.f, cnt = 0.f;
    float bf = cb[f];
    for (int n = n0; n < n1; ++n) {
        int gid = batch[n];
        if (gid != cur) {
            atomicAdd(&g_sums[cur * FF + f], acc);
            if (f == 0) atomicAdd(&g_cnt[cur], cnt);
            acc = 0.f; cnt = 0.f; cur = gid;
        }
        acc += g_agg[(size_t)n * FF + f] + bf;
        cnt += 1.f;
    }
    atomicAdd(&g_sums[cur * FF + f], acc);
    if (f == 0) atomicAdd(&g_cnt[cur], cnt);
}

// ------------------- out = (sums/cnt) @ lin_w + lin_b -------------------
__global__ void __launch_bounds__(128) k_out(const float* __restrict__ lin_w,
                                             const float* __restrict__ lin_b,
                                             float* __restrict__ out) {
    __shared__ float p[FF];
    int g = blockIdx.x;
    int t = threadIdx.x;
    float c = g_cnt[g];
    float inv = 1.f / fmaxf(c, 1.f);
    p[t] = g_sums[g * FF + t] * inv;
    __syncthreads();
    if (t < CC) {
        float acc = lin_b[t];
#pragma unroll
        for (int k = 0; k < FF; k++) acc += p[k] * lin_w[k * CC + t];
        out[g * CC + t] = acc;
    }
}

// ------------------- launch -------------------
extern "C" void kernel_launch(void* const* d_in, const int* in_sizes, int n_in,
                              void* d_out, int out_size) {
    const float* x      = (const float*)d_in[0];
    const int*   ei     = (const int*)d_in[1];      // int32 (JAX x64 disabled)
    const int*   batch  = (const int*)d_in[2];      // int32
    const float* conv_w = (const float*)d_in[3];
    const float* conv_b = (const float*)d_in[4];
    const float* bn_g   = (const float*)d_in[5];
    const float* bn_b   = (const float*)d_in[6];
    const float* bn_m   = (const float*)d_in[7];
    const float* bn_v   = (const float*)d_in[8];
    const float* lin_w  = (const float*)d_in[9];
    const float* lin_b  = (const float*)d_in[10];
    float*       out    = (float*)d_out;

    float* h_ptr; cudaGetSymbolAddress((void**)&h_ptr, g_h);

    const int TB = 256;
    // unordered-CSR build (once; reused by all 3 layers)
    k_init<<<(NN + TB - 1) / TB, TB>>>();
    k_histo<<<(EE + TB - 1) / TB, TB>>>(ei);
    k_seg<<<(NN + TB - 1) / TB, TB>>>();
    k_fill<<<(EE + TB - 1) / TB, TB>>>(ei);

    const int GEMM_BLOCKS = (NN + 63) / 64;
    const int AGG_BLOCKS = (NN * 32 + TB - 1) / TB;

    for (int l = 0; l < 3; ++l) {
        const float* hin = (l == 0) ? x : h_ptr;
        k_gemm<<<GEMM_BLOCKS, 256>>>(hin, conv_w + (size_t)l * FF * FF);
        if (l < 2) {
            k_agg_bn<<<AGG_BLOCKS, TB>>>(conv_b + l * FF, bn_g + l * FF, bn_b + l * FF,
                                         bn_m + l * FF, bn_v + l * FF);
        } else {
            k_agg_raw<<<AGG_BLOCKS, TB>>>();
            k_pool<<<(NN + PCH - 1) / PCH, 128>>>(conv_b + l * FF, batch);
        }
    }
    k_out<<<GG, 128>>>(lin_w, lin_b, out);
}

// round 17
// speedup vs baseline: 5.3243x; 1.4431x over previous
#include <cuda_runtime.h>
#include <cuda_fp16.h>

#define NN 100000
#define EE 1600000
#define FF 128
#define GG 512
#define CC 40
#define BN_EPS 1e-5f

// ------------------- scratch (device globals; no allocation) -------------------
__device__ int   g_count[NN];
__device__ float g_dinv[NN];
__device__ int   g_rowbeg[NN];
__device__ int   g_cursor[NN];
__device__ int   g_total;
__device__ __align__(8) int2 g_edge[EE];                  // {src, norm_bits} grouped by dst
__device__ __align__(16) __half g_ah[(size_t)NN * FF];    // fp16 GEMM input (x or h)
__device__ __align__(16) __half g_wh[3 * FF * FF];        // fp16 weights
__device__ __align__(16) __half g_xwh[(size_t)NN * FF];   // fp16 xw (gather payload)
__device__ __align__(16) float g_agg[(size_t)NN * FF];
__device__ float g_sums[GG * FF];
__device__ float g_cnt[GG];

__device__ __forceinline__ unsigned h2u(__half2 h) { return *(unsigned*)&h; }
__device__ __forceinline__ __half2 u2h(unsigned u) { return *(__half2*)&u; }

// ------------------- setup kernels -------------------
__global__ void k_init() {
    int i = blockIdx.x * blockDim.x + threadIdx.x;
    if (i < NN) g_count[i] = 0;
    if (i < GG * FF) g_sums[i] = 0.f;
    if (i < GG) g_cnt[i] = 0.f;
    if (i == 0) g_total = 0;
}

__global__ void k_histo(const int* __restrict__ ei) {
    int e = blockIdx.x * blockDim.x + threadIdx.x;
    if (e < EE) atomicAdd(&g_count[ei[EE + e]], 1);
}

__global__ void k_seg() {
    int i = blockIdx.x * blockDim.x + threadIdx.x;
    if (i < NN) {
        int c = g_count[i];
        g_dinv[i] = rsqrtf((float)c + 1.f);
        int start = atomicAdd(&g_total, c);
        g_rowbeg[i] = start;
        g_cursor[i] = start;
    }
}

__global__ void k_fill(const int* __restrict__ ei) {
    int e = blockIdx.x * blockDim.x + threadIdx.x;
    if (e < EE) {
        int s = ei[e];
        int d = ei[EE + e];
        float nv = g_dinv[s] * g_dinv[d];
        int pos = atomicAdd(&g_cursor[d], 1);
        g_edge[pos] = make_int2(s, __float_as_int(nv));
    }
}

// convert x (fp32) -> g_ah (fp16); 8 elems/thread
__global__ void k_xcvt(const float* __restrict__ x) {
    size_t i = (size_t)(blockIdx.x * blockDim.x + threadIdx.x);
    if (i >= (size_t)NN * FF / 8) return;
    float4 a = *(const float4*)(x + i * 8);
    float4 b = *(const float4*)(x + i * 8 + 4);
    uint4 o;
    o.x = h2u(__floats2half2_rn(a.x, a.y));
    o.y = h2u(__floats2half2_rn(a.z, a.w));
    o.z = h2u(__floats2half2_rn(b.x, b.y));
    o.w = h2u(__floats2half2_rn(b.z, b.w));
    *(uint4*)(g_ah + i * 8) = o;
}

// convert all 3 conv_w layers to fp16
__global__ void k_wcvt(const float* __restrict__ w) {
    int i = blockIdx.x * blockDim.x + threadIdx.x;
    if (i < 3 * FF * FF / 2) {
        float2 v = *(const float2*)(w + (size_t)i * 2);
        *(unsigned*)(g_wh + (size_t)i * 2) = h2u(__floats2half2_rn(v.x, v.y));
    }
}

// ------------------- tensor-core GEMM: xwh = fp16( Ah @ Wh ) -------------------
// Block 256 thr (8 warps), tile 128 rows x 128 cols, K=128 in 2 chunks of 64.
// warp w owns rows w*16..w*16+15. mma.sync m16n8k16 f32 accum.
#define APAD 8
#define WPAD 8
__global__ void __launch_bounds__(256) k_gemm_tc(const __half* __restrict__ Ah,
                                                 const __half* __restrict__ Wh) {
    __shared__ __half Ash[128][64 + APAD];
    __shared__ __half Wsh[64][128 + WPAD];
    int tid = threadIdx.x;
    int warp = tid >> 5;
    int lane = tid & 31;
    int r0 = blockIdx.x * 128;

    float acc[16][4];
#pragma unroll
    for (int n = 0; n < 16; n++)
#pragma unroll
        for (int j = 0; j < 4; j++) acc[n][j] = 0.f;

    for (int kk = 0; kk < 128; kk += 64) {
        // stage A chunk: 128 rows x 64 halves
#pragma unroll
        for (int t = 0; t < 4; t++) {
            int idx = tid + t * 256;        // 0..1023
            int row = idx >> 3;
            int c = idx & 7;
            uint4 v = make_uint4(0u, 0u, 0u, 0u);
            if (r0 + row < NN)
                v = *(const uint4*)(Ah + (size_t)(r0 + row) * FF + kk + c * 8);
            *(uint4*)(&Ash[row][c * 8]) = v;
        }
        // stage W chunk: 64 rows x 128 halves
#pragma unroll
        for (int t = 0; t < 4; t++) {
            int idx = tid + t * 256;        // 0..1023
            int row = idx >> 4;
            int c = idx & 15;
            *(uint4*)(&Wsh[row][c * 8]) =
                *(const uint4*)(Wh + (size_t)(kk + row) * FF + c * 8);
        }
        __syncthreads();

#pragma unroll
        for (int ks = 0; ks < 4; ks++) {
            int k0 = ks * 16;
            // A fragment (m16 k16) via ldmatrix x4
            unsigned a0, a1, a2, a3;
            {
                const __half* p = &Ash[warp * 16 + (lane & 15)][k0 + (lane >> 4) * 8];
                unsigned addr = (unsigned)__cvta_generic_to_shared(p);
                asm volatile("ldmatrix.sync.aligned.m8n8.x4.shared.b16 {%0,%1,%2,%3}, [%4];"
                             : "=r"(a0), "=r"(a1), "=r"(a2), "=r"(a3) : "r"(addr));
            }
#pragma unroll
            for (int nf = 0; nf < 8; nf++) {
                int n0 = nf * 16;
                unsigned b0, b1, b2, b3;
                {
                    const __half* p = &Wsh[k0 + (lane & 15)][n0 + (lane >> 4) * 8];
                    unsigned addr = (unsigned)__cvta_generic_to_shared(p);
                    asm volatile("ldmatrix.sync.aligned.m8n8.x4.trans.shared.b16 {%0,%1,%2,%3}, [%4];"
                                 : "=r"(b0), "=r"(b1), "=r"(b2), "=r"(b3) : "r"(addr));
                }
                float* c0 = acc[nf * 2];
                float* c1 = acc[nf * 2 + 1];
                asm volatile("mma.sync.aligned.m16n8k16.row.col.f32.f16.f16.f32 "
                             "{%0,%1,%2,%3}, {%4,%5,%6,%7}, {%8,%9}, {%0,%1,%2,%3};"
                             : "+f"(c0[0]), "+f"(c0[1]), "+f"(c0[2]), "+f"(c0[3])
                             : "r"(a0), "r"(a1), "r"(a2), "r"(a3), "r"(b0), "r"(b1));
                asm volatile("mma.sync.aligned.m16n8k16.row.col.f32.f16.f16.f32 "
                             "{%0,%1,%2,%3}, {%4,%5,%6,%7}, {%8,%9}, {%0,%1,%2,%3};"
                             : "+f"(c1[0]), "+f"(c1[1]), "+f"(c1[2]), "+f"(c1[3])
                             : "r"(a0), "r"(a1), "r"(a2), "r"(a3), "r"(b2), "r"(b3));
            }
        }
        __syncthreads();
    }

    // epilogue: fp16 store. c0/c1 -> row lane/4, cols (lane%4)*2; c2/c3 -> row+8
    int rbase = r0 + warp * 16 + (lane >> 2);
    int cbase = (lane & 3) * 2;
#pragma unroll
    for (int nf = 0; nf < 16; nf++) {
        int col = nf * 8 + cbase;
        if (rbase < NN)
            *(unsigned*)(g_xwh + (size_t)rbase * FF + col) =
                h2u(__floats2half2_rn(acc[nf][0], acc[nf][1]));
        if (rbase + 8 < NN)
            *(unsigned*)(g_xwh + (size_t)(rbase + 8) * FF + col) =
                h2u(__floats2half2_rn(acc[nf][2], acc[nf][3]));
    }
}

// ------------------- gather aggregation: warp per node ------------------------
__device__ __forceinline__ float4 h4_to_f4(uint2 raw) {
    float2 lo = __half22float2(u2h(raw.x));
    float2 hi = __half22float2(u2h(raw.y));
    return make_float4(lo.x, lo.y, hi.x, hi.y);
}

__device__ __forceinline__ float4 agg_node(int w, int lane) {
    int f4 = lane * 4;
    float di = g_dinv[w];
    float sl = di * di;
    float4 xs = h4_to_f4(__ldg((const uint2*)(g_xwh + (size_t)w * FF + f4)));
    float4 acc = make_float4(xs.x * sl, xs.y * sl, xs.z * sl, xs.w * sl);
    int beg = g_rowbeg[w];
    int end = beg + g_count[w];
    int e = beg;
    for (; e + 1 < end; e += 2) {
        int2 e0 = __ldg(&g_edge[e]);
        int2 e1 = __ldg(&g_edge[e + 1]);
        float4 v0 = h4_to_f4(__ldg((const uint2*)(g_xwh + (size_t)e0.x * FF + f4)));
        float4 v1 = h4_to_f4(__ldg((const uint2*)(g_xwh + (size_t)e1.x * FF + f4)));
        float n0 = __int_as_float(e0.y);
        float n1 = __int_as_float(e1.y);
        acc.x = fmaf(v0.x, n0, acc.x); acc.y = fmaf(v0.y, n0, acc.y);
        acc.z = fmaf(v0.z, n0, acc.z); acc.w = fmaf(v0.w, n0, acc.w);
        acc.x = fmaf(v1.x, n1, acc.x); acc.y = fmaf(v1.y, n1, acc.y);
        acc.z = fmaf(v1.z, n1, acc.z); acc.w = fmaf(v1.w, n1, acc.w);
    }
    if (e < end) {
        int2 ed = __ldg(&g_edge[e]);
        float nv = __int_as_float(ed.y);
        float4 v = h4_to_f4(__ldg((const uint2*)(g_xwh + (size_t)ed.x * FF + f4)));
        acc.x = fmaf(v.x, nv, acc.x); acc.y = fmaf(v.y, nv, acc.y);
        acc.z = fmaf(v.z, nv, acc.z); acc.w = fmaf(v.w, nv, acc.w);
    }
    return acc;
}

// BN+ReLU epilogue, fp16 output (next GEMM's input)
__global__ void __launch_bounds__(256) k_agg_bn(const float* __restrict__ cb,
                                                const float* __restrict__ gm,
                                                const float* __restrict__ bt,
                                                const float* __restrict__ mn,
                                                const float* __restrict__ vr) {
    int w = (blockIdx.x * 256 + threadIdx.x) >> 5;
    int lane = threadIdx.x & 31;
    if (w >= NN) return;
    float4 acc = agg_node(w, lane);
    int f4 = lane * 4;
    float4 b  = *(const float4*)(cb + f4);
    float4 g  = *(const float4*)(gm + f4);
    float4 be = *(const float4*)(bt + f4);
    float4 m  = *(const float4*)(mn + f4);
    float4 v  = *(const float4*)(vr + f4);
    float4 o;
    o.x = fmaxf((acc.x + b.x - m.x) * (g.x * rsqrtf(v.x + BN_EPS)) + be.x, 0.f);
    o.y = fmaxf((acc.y + b.y - m.y) * (g.y * rsqrtf(v.y + BN_EPS)) + be.y, 0.f);
    o.z = fmaxf((acc.z + b.z - m.z) * (g.z * rsqrtf(v.z + BN_EPS)) + be.z, 0.f);
    o.w = fmaxf((acc.w + b.w - m.w) * (g.w * rsqrtf(v.w + BN_EPS)) + be.w, 0.f);
    uint2 oh;
    oh.x = h2u(__floats2half2_rn(o.x, o.y));
    oh.y = h2u(__floats2half2_rn(o.z, o.w));
    *(uint2*)(g_ah + (size_t)w * FF + f4) = oh;
}

__global__ void __launch_bounds__(256) k_agg_raw() {
    int w = (blockIdx.x * 256 + threadIdx.x) >> 5;
    int lane = threadIdx.x & 31;
    if (w >= NN) return;
    float4 acc = agg_node(w, lane);
    *(float4*)(g_agg + (size_t)w * FF + lane * 4) = acc;
}

// ------------------- pooled sums over sorted batch + final bias ---------------
#define PCH 64
__global__ void __launch_bounds__(128) k_pool(const float* __restrict__ cb,
                                              const int* __restrict__ batch) {
    int f = threadIdx.x;
    int n0 = blockIdx.x * PCH;
    if (n0 >= NN) return;
    int n1 = n0 + PCH; if (n1 > NN) n1 = NN;
    int cur = batch[n0];
    float acc = 0.f, cnt = 0.f;
    float bf = cb[f];
    for (int n = n0; n < n1; ++n) {
        int gid = batch[n];
        if (gid != cur) {
            atomicAdd(&g_sums[cur * FF + f], acc);
            if (f == 0) atomicAdd(&g_cnt[cur], cnt);
            acc = 0.f; cnt = 0.f; cur = gid;
        }
        acc += g_agg[(size_t)n * FF + f] + bf;
        cnt += 1.f;
    }
    atomicAdd(&g_sums[cur * FF + f], acc);
    if (f == 0) atomicAdd(&g_cnt[cur], cnt);
}

// ------------------- out = (sums/cnt) @ lin_w + lin_b -------------------
__global__ void __launch_bounds__(128) k_out(const float* __restrict__ lin_w,
                                             const float* __restrict__ lin_b,
                                             float* __restrict__ out) {
    __shared__ float p[FF];
    int g = blockIdx.x;
    int t = threadIdx.x;
    float c = g_cnt[g];
    float inv = 1.f / fmaxf(c, 1.f);
    p[t] = g_sums[g * FF + t] * inv;
    __syncthreads();
    if (t < CC) {
        float acc = lin_b[t];
#pragma unroll
        for (int k = 0; k < FF; k++) acc += p[k] * lin_w[k * CC + t];
        out[g * CC + t] = acc;
    }
}

// ------------------- launch -------------------
extern "C" void kernel_launch(void* const* d_in, const int* in_sizes, int n_in,
                              void* d_out, int out_size) {
    const float* x      = (const float*)d_in[0];
    const int*   ei     = (const int*)d_in[1];      // int32 (JAX x64 disabled)
    const int*   batch  = (const int*)d_in[2];      // int32
    const float* conv_w = (const float*)d_in[3];
    const float* conv_b = (const float*)d_in[4];
    const float* bn_g   = (const float*)d_in[5];
    const float* bn_b   = (const float*)d_in[6];
    const float* bn_m   = (const float*)d_in[7];
    const float* bn_v   = (const float*)d_in[8];
    const float* lin_w  = (const float*)d_in[9];
    const float* lin_b  = (const float*)d_in[10];
    float*       out    = (float*)d_out;

    __half* ah_ptr; cudaGetSymbolAddress((void**)&ah_ptr, g_ah);
    __half* wh_ptr; cudaGetSymbolAddress((void**)&wh_ptr, g_wh);

    const int TB = 256;
    // unordered-CSR build + fp16 conversions (once)
    k_init<<<(NN + TB - 1) / TB, TB>>>();
    k_histo<<<(EE + TB - 1) / TB, TB>>>(ei);
    k_seg<<<(NN + TB - 1) / TB, TB>>>();
    k_fill<<<(EE + TB - 1) / TB, TB>>>(ei);
    k_xcvt<<<(NN * FF / 8 + TB - 1) / TB, TB>>>(x);
    k_wcvt<<<(3 * FF * FF / 2 + TB - 1) / TB, TB>>>(conv_w);

    const int GEMM_BLOCKS = (NN + 127) / 128;
    const int AGG_BLOCKS = (NN * 32 + TB - 1) / TB;

    for (int l = 0; l < 3; ++l) {
        k_gemm_tc<<<GEMM_BLOCKS, 256>>>(ah_ptr, wh_ptr + (size_t)l * FF * FF);
        if (l < 2) {
            k_agg_bn<<<AGG_BLOCKS, TB>>>(conv_b + l * FF, bn_g + l * FF, bn_b + l * FF,
                                         bn_m + l * FF, bn_v + l * FF);
        } else {
            k_agg_raw<<<AGG_BLOCKS, TB>>>();
            k_pool<<<(NN + PCH - 1) / PCH, 128>>>(conv_b + l * FF, batch);
        }
    }
    k_out<<<GG, 128>>>(lin_w, lin_b, out);
}